// round 10
// baseline (speedup 1.0000x reference)
#include <cuda_runtime.h>
#include <cuda_bf16.h>
#include <math.h>

// Problem constants
#define NN   50000
#define EE   800000
#define NMOL 2000
#define INRR 64
#define OUTD 128
#define EDD  16
#define CLSD 256
#define HSW  640   // OUT*(L_CONV+1)

// Static scratch (no allocations allowed)
__device__ float g_agg[(size_t)NN * 128];
__device__ float g_h0[(size_t)NN * 128];
__device__ float g_HS[(size_t)NN * HSW];
__device__ float g_pool[(size_t)NMOL * 128];
__device__ float g_z1[(size_t)NN * CLSD];
__device__ float g_z2[(size_t)NN * CLSD];
// CSR (by dst) — g_cnt zero at load; csr_scan re-zeroes it each call.
__device__ int g_cnt[NN];
__device__ int g_off[NN + 1];
__device__ int g_cur[NN];
__device__ int g_srcs[EE];                       // CSR-ordered src node
__device__ float g_attrs[(size_t)EE * 16];       // CSR-ordered edge_attr

// Pre-converted packed bf16 weights (hi/lo split).
#define WC1_OFF   0                 // conv1W:  Kp=32,  M=128 -> 4096
#define WCV_OFF   4096              // convW i: Kp=64,  M=128 -> 8192 each (x4)
#define WK1_OFF   36864             // cls1W:   Kp=320, M=256 -> 81920
#define WK2_OFF   118784            // kW[0]:   Kp=128, M=256 -> 32768
#define WK3_OFF   151552            // kW[1]:   Kp=128, M=256 -> 32768
#define WTOT      184320
__device__ unsigned g_Bh[WTOT];
__device__ unsigned g_Bl[WTOT];

__device__ __forceinline__ float dleaky(float v) {
    float t = v > 0.f ? v : 0.01f * v;
    return t > 0.f ? t : 0.01f * t;
}
__device__ __forceinline__ float leaky1(float v) {
    return v > 0.f ? v : 0.01f * v;
}

// f32x2 helpers
__device__ __forceinline__ unsigned long long packf2(float lo, float hi) {
    unsigned long long r;
    asm("mov.b64 %0, {%1, %2};" : "=l"(r) : "r"(__float_as_uint(lo)), "r"(__float_as_uint(hi)));
    return r;
}
__device__ __forceinline__ unsigned long long dupf2(float v) {
    unsigned long long r;
    unsigned b = __float_as_uint(v);
    asm("mov.b64 %0, {%1, %1};" : "=l"(r) : "r"(b));
    return r;
}
__device__ __forceinline__ void fma2(unsigned long long& d,
                                     unsigned long long a, unsigned long long b) {
    asm("fma.rn.f32x2 %0, %1, %2, %0;" : "+l"(d) : "l"(a), "l"(b));
}
__device__ __forceinline__ void unpackf2(unsigned long long v, float& lo, float& hi) {
    unsigned ulo, uhi;
    asm("mov.b64 {%0, %1}, %2;" : "=r"(ulo), "=r"(uhi) : "l"(v));
    lo = __uint_as_float(ulo);
    hi = __uint_as_float(uhi);
}

__device__ __forceinline__ unsigned pack_bf16(float lo, float hi) {
    __nv_bfloat162 h = __floats2bfloat162_rn(lo, hi);
    return *(unsigned*)&h;
}

// ---------------------------------------------------------------------------
// Fused: blocks [0, CNT_BLK) count edge dst; rest convert weights to bf16 hi/lo
// ---------------------------------------------------------------------------
#define CNT_BLK 3125                 // ceil(EE/256)
#define WCVT_BLK 720                 // ceil(WTOT/256)

__global__ void wcvt_count_kernel(const int* __restrict__ dstv,
                                  const float* __restrict__ c1W,
                                  const float* __restrict__ cW,
                                  const float* __restrict__ k1W,
                                  const float* __restrict__ kW) {
    if (blockIdx.x < CNT_BLK) {
        int e = blockIdx.x * blockDim.x + threadIdx.x;
        if (e < EE) atomicAdd(&g_cnt[dstv[e]], 1);
        return;
    }
    int widx = (blockIdx.x - CNT_BLK) * blockDim.x + threadIdx.x;
    if (widx >= WTOT) return;
    const float* src;
    int M, kp, m;
    if (widx < WCV_OFF) {
        src = c1W; M = 128;
        kp = widx >> 7; m = widx & 127;
    } else if (widx < WK1_OFF) {
        int r = widx - WCV_OFF;
        int i = r >> 13; r &= 8191;
        src = cW + (size_t)i * OUTD * OUTD; M = 128;
        kp = r >> 7; m = r & 127;
    } else if (widx < WK2_OFF) {
        int r = widx - WK1_OFF;
        src = k1W; M = 256;
        kp = r >> 8; m = r & 255;
    } else if (widx < WK3_OFF) {
        int r = widx - WK2_OFF;
        src = kW; M = 256;
        kp = r >> 8; m = r & 255;
    } else {
        int r = widx - WK3_OFF;
        src = kW + CLSD * CLSD; M = 256;
        kp = r >> 8; m = r & 255;
    }
    float v0 = src[(size_t)(2 * kp) * M + m];
    float v1 = src[(size_t)(2 * kp + 1) * M + m];
    float h0 = __bfloat162float(__float2bfloat16(v0));
    float h1 = __bfloat162float(__float2bfloat16(v1));
    g_Bh[widx] = pack_bf16(h0, h1);
    g_Bl[widx] = pack_bf16(v0 - h0, v1 - h1);
}

// ---------------------------------------------------------------------------
// Scan: g_cnt -> g_off/g_cur, then zero g_cnt
// ---------------------------------------------------------------------------
__global__ void csr_scan_kernel() {
    __shared__ int part[1024];
    const int CH = (NN + 1023) / 1024;
    int t = threadIdx.x;
    int start = t * CH;
    int sum = 0;
    for (int i = 0; i < CH; i++) {
        int idx = start + i;
        if (idx < NN) sum += g_cnt[idx];
    }
    part[t] = sum;
    __syncthreads();
    for (int o = 1; o < 1024; o <<= 1) {
        int v = (t >= o) ? part[t - o] : 0;
        __syncthreads();
        part[t] += v;
        __syncthreads();
    }
    int run = part[t] - sum;
    for (int i = 0; i < CH; i++) {
        int idx = start + i;
        if (idx < NN) {
            g_off[idx] = run;
            g_cur[idx] = run;
            run += g_cnt[idx];
            g_cnt[idx] = 0;
        }
    }
    if (t == 0) g_off[NN] = EE;
}

// ---------------------------------------------------------------------------
// Fill + permute fused: 4 threads per edge.
// ---------------------------------------------------------------------------
__global__ void fill_permute_kernel(const int* __restrict__ srcv,
                                    const int* __restrict__ dstv,
                                    const float* __restrict__ attr) {
    int idx = blockIdx.x * blockDim.x + threadIdx.x;   // EE*4
    if (idx >= EE * 4) return;
    int e = idx >> 2, c4 = idx & 3;
    int lane = threadIdx.x & 31;
    int pos = 0;
    if (c4 == 0) pos = atomicAdd(&g_cur[dstv[e]], 1);
    pos = __shfl_sync(0xffffffffu, pos, lane & ~3);
    float4 v = __ldg((const float4*)&attr[(size_t)e * 16 + c4 * 4]);
    *(float4*)&g_attrs[(size_t)pos * 16 + c4 * 4] = v;
    if (c4 == 0) g_srcs[pos] = __ldg(&srcv[e]);
}

// ---------------------------------------------------------------------------
// Gather with cp.async smem ring: warp per node, 6-edge lookahead.
//   agg[n] = x[n] + sum_{e: dst=n} relu(x[src[e]] + attr[e]@eW + eb)
// C = floats per lane (2 for D=64, 4 for D=128).
// WSMEM (C=4): weights in smem, ONE ulonglong2 (16B) per (k,lane) ->
// conflict-free LDS.128 (consecutive lanes at consecutive 16B).
// ---------------------------------------------------------------------------
template <int C, bool WSMEM>
__global__ __launch_bounds__(128, 8)
void gather_kernel(const float* __restrict__ x, int ldx,
                   const float* __restrict__ eW,
                   const float* __restrict__ eb,
                   float* __restrict__ agg) {
    constexpr int D = C * 32;
    constexpr int XB = 128 * C;        // x-row bytes per warp
    constexpr int SLOT = XB + 64;      // + attr
    constexpr int NS = 8;              // ring slots (power of 2)
    constexpr int LA = 6;              // lookahead depth

    __shared__ __align__(16) char s_ring[4 * NS * SLOT];
    __shared__ __align__(16) ulonglong2 s_w2[WSMEM ? 16 * 32 : 1];

    const int tid = threadIdx.x;
    const int lane = tid & 31;
    const int wIn = tid >> 5;
    char* ring = s_ring + wIn * (NS * SLOT);

    if constexpr (WSMEM) {
        // s_w2[k*32 + l] = { pack(eW[k][4l], eW[k][4l+1]), pack(eW[k][4l+2], eW[k][4l+3]) }
        for (int i = tid; i < 16 * 32; i += 128) {
            int k = i >> 5, l = i & 31;
            const float* wr = &eW[k * D + 4 * l];
            s_w2[i] = make_ulonglong2(packf2(wr[0], wr[1]), packf2(wr[2], wr[3]));
        }
        __syncthreads();
    }

    const int n = (blockIdx.x * blockDim.x + tid) >> 5;
    if (n >= NN) return;
    const int colf = lane * C;

    unsigned long long wp[WSMEM ? 1 : 16 * (C / 2)];
    if constexpr (!WSMEM) {
#pragma unroll
        for (int k = 0; k < 16; k++)
#pragma unroll
            for (int p = 0; p < C / 2; p++)
                wp[k * (C / 2) + p] = packf2(eW[k * D + colf + 2 * p],
                                             eW[k * D + colf + 2 * p + 1]);
    }
    unsigned long long ebp[C / 2];
#pragma unroll
    for (int p = 0; p < C / 2; p++)
        ebp[p] = packf2(eb[colf + 2 * p], eb[colf + 2 * p + 1]);

    const int i0 = __ldg(&g_off[n]);
    const int i1 = __ldg(&g_off[n + 1]);

    float acc[C];
    if constexpr (C == 4) {
        float4 xv = *(const float4*)&x[(size_t)n * ldx + colf];
        acc[0] = xv.x; acc[1] = xv.y; acc[2] = xv.z; acc[3] = xv.w;
    } else {
        float2 xv = *(const float2*)&x[(size_t)n * ldx + colf];
        acc[0] = xv.x; acc[1] = xv.y;
    }

    auto issue = [&](int pos, int s) {
        if (pos < i1) {
            char* sp = ring + (pos & (NS - 1)) * SLOT;
            const float* grow = x + (size_t)s * ldx + colf;
            unsigned sx = (unsigned)__cvta_generic_to_shared(sp) + lane * (C * 4);
            if constexpr (C == 4)
                asm volatile("cp.async.ca.shared.global [%0], [%1], 16;"
                             :: "r"(sx), "l"(grow));
            else
                asm volatile("cp.async.ca.shared.global [%0], [%1], 8;"
                             :: "r"(sx), "l"(grow));
            if (lane < 4) {
                const float* ga = g_attrs + (size_t)pos * 16 + lane * 4;
                unsigned sa = (unsigned)__cvta_generic_to_shared(sp) + XB + lane * 16;
                asm volatile("cp.async.ca.shared.global [%0], [%1], 16;"
                             :: "r"(sa), "l"(ga));
            }
        }
        asm volatile("cp.async.commit_group;" ::: "memory");
    };

    // prologue: issue LA edges (src prefetched one ahead)
    int s_pf = (i0 < i1) ? __ldg(&g_srcs[i0]) : 0;
#pragma unroll
    for (int j = 0; j < LA; j++) {
        int p = i0 + j;
        int s_nx = (p + 1 < i1) ? __ldg(&g_srcs[p + 1]) : 0;
        issue(p, s_pf);
        s_pf = s_nx;
    }

    for (int pos = i0; pos < i1; pos++) {
        int p = pos + LA;
        int s_nx = (p + 1 < i1) ? __ldg(&g_srcs[p + 1]) : 0;
        issue(p, s_pf);
        s_pf = s_nx;

        asm volatile("cp.async.wait_group 6;" ::: "memory");
        __syncwarp();

        const char* sp = ring + (pos & (NS - 1)) * SLOT;
        const float4* ap = (const float4*)(sp + XB);
        float4 A0 = ap[0], A1 = ap[1], A2 = ap[2], A3 = ap[3];
        float av[16] = {A0.x, A0.y, A0.z, A0.w, A1.x, A1.y, A1.z, A1.w,
                        A2.x, A2.y, A2.z, A2.w, A3.x, A3.y, A3.z, A3.w};
        unsigned long long e[C / 2];
#pragma unroll
        for (int q = 0; q < C / 2; q++) e[q] = ebp[q];
#pragma unroll
        for (int k = 0; k < 16; k++) {
            unsigned long long a2 = dupf2(av[k]);
            if constexpr (WSMEM) {
                ulonglong2 w = s_w2[k * 32 + lane];   // LDS.128 conflict-free
                fma2(e[0], a2, w.x);
                if constexpr (C == 4) fma2(e[1], a2, w.y);
            } else {
#pragma unroll
                for (int q = 0; q < C / 2; q++)
                    fma2(e[q], a2, wp[k * (C / 2) + q]);
            }
        }
#pragma unroll
        for (int q = 0; q < C / 2; q++) {
            float lo, hi;
            unpackf2(e[q], lo, hi);
            float2 xr = *(const float2*)(sp + lane * (C * 4) + q * 8);
            float m0 = xr.x + lo;
            float m1 = xr.y + hi;
            acc[2 * q] += m0 > 0.f ? m0 : 0.f;
            acc[2 * q + 1] += m1 > 0.f ? m1 : 0.f;
        }
    }

    if constexpr (C == 4) {
        *(float4*)&g_agg[(size_t)n * D + colf] =
            make_float4(acc[0], acc[1], acc[2], acc[3]);
    } else {
        *(float2*)&g_agg[(size_t)n * D + colf] = make_float2(acc[0], acc[1]);
    }
}

// ---------------------------------------------------------------------------
// Split-bf16 tensor-core GEMM with pre-converted packed B.
// ---------------------------------------------------------------------------
__device__ __forceinline__ void mma_bf16(float* acc, const unsigned* a, const unsigned* b) {
    asm volatile(
        "mma.sync.aligned.m16n8k16.row.col.f32.bf16.bf16.f32 "
        "{%0,%1,%2,%3}, {%4,%5,%6,%7}, {%8,%9}, {%0,%1,%2,%3};"
        : "+f"(acc[0]), "+f"(acc[1]), "+f"(acc[2]), "+f"(acc[3])
        : "r"(a[0]), "r"(a[1]), "r"(a[2]), "r"(a[3]), "r"(b[0]), "r"(b[1]));
}

template <int ACT>
__global__ __launch_bounds__(256)
void bf16_gemm(const float* __restrict__ A, int lda,
               const unsigned* __restrict__ PBh,
               const unsigned* __restrict__ PBl,
               const float* __restrict__ bias,
               const float* __restrict__ gamma,
               const float* __restrict__ beta,
               float* __restrict__ Cmat, int ldc,
               int Nrows, int K, int M, float bn_inv) {
    __shared__ unsigned sAh[128][9];
    __shared__ unsigned sAl[128][9];
    __shared__ unsigned sBh[128][9];
    __shared__ unsigned sBl[128][9];

    const int tid = threadIdx.x;
    const int lane = tid & 31;
    const int wid = tid >> 5;
    const int wm = (wid & 1) * 64;
    const int wn = (wid >> 1) * 32;
    const int row0 = blockIdx.y * 128;
    const int col0 = blockIdx.x * 128;

    float acc[16][4];
#pragma unroll
    for (int i = 0; i < 16; i++)
#pragma unroll
        for (int j = 0; j < 4; j++) acc[i][j] = 0.f;

    float4 ga[2];
    uint2 gh[2], gl[2];

    auto load_tile = [&](int k0) {
#pragma unroll
        for (int j = 0; j < 2; j++) {
            int idx = j * 256 + tid;
            int m = idx >> 2, kk = (idx & 3) << 2;
            int r = row0 + m;
            ga[j] = make_float4(0.f, 0.f, 0.f, 0.f);
            if (r < Nrows) ga[j] = *(const float4*)&A[(size_t)r * lda + k0 + kk];
            int n = (idx & 63) << 1, bkp = idx >> 6;
            size_t off = (size_t)(k0 / 2 + bkp) * M + col0 + n;
            gh[j] = *(const uint2*)&PBh[off];
            gl[j] = *(const uint2*)&PBl[off];
        }
    };

    load_tile(0);

    for (int k0 = 0; k0 < K; k0 += 16) {
        __syncthreads();
#pragma unroll
        for (int j = 0; j < 2; j++) {
            int idx = j * 256 + tid;
            int m = idx >> 2, kp = (idx & 3) << 1;
            float4 v = ga[j];
            float hx = __bfloat162float(__float2bfloat16(v.x));
            float hy = __bfloat162float(__float2bfloat16(v.y));
            float hz = __bfloat162float(__float2bfloat16(v.z));
            float hw = __bfloat162float(__float2bfloat16(v.w));
            sAh[m][kp]     = pack_bf16(hx, hy);
            sAh[m][kp + 1] = pack_bf16(hz, hw);
            sAl[m][kp]     = pack_bf16(v.x - hx, v.y - hy);
            sAl[m][kp + 1] = pack_bf16(v.z - hz, v.w - hw);

            int n = (idx & 63) << 1, bkp = idx >> 6;
            sBh[n][bkp]     = gh[j].x;
            sBh[n + 1][bkp] = gh[j].y;
            sBl[n][bkp]     = gl[j].x;
            sBl[n + 1][bkp] = gl[j].y;
        }
        __syncthreads();

        if (k0 + 16 < K) load_tile(k0 + 16);

        unsigned af[4][4], bh[4][2], bl[4][2];
        const int ar = lane >> 2, ak = lane & 3;
#pragma unroll
        for (int i = 0; i < 4; i++) {
            int m = wm + i * 16 + ar;
            af[i][0] = sAh[m][ak];
            af[i][1] = sAh[m + 8][ak];
            af[i][2] = sAh[m][ak + 4];
            af[i][3] = sAh[m + 8][ak + 4];
        }
#pragma unroll
        for (int j = 0; j < 4; j++) {
            int nn = wn + j * 8 + (lane >> 2);
            bh[j][0] = sBh[nn][lane & 3];
            bh[j][1] = sBh[nn][(lane & 3) + 4];
            bl[j][0] = sBl[nn][lane & 3];
            bl[j][1] = sBl[nn][(lane & 3) + 4];
        }
#pragma unroll
        for (int i = 0; i < 4; i++)
#pragma unroll
            for (int j = 0; j < 4; j++) mma_bf16(acc[i * 4 + j], af[i], bh[j]);
#pragma unroll
        for (int i = 0; i < 4; i++)
#pragma unroll
            for (int j = 0; j < 4; j++) mma_bf16(acc[i * 4 + j], af[i], bl[j]);
#pragma unroll
        for (int i = 0; i < 4; i++) {
            int m = wm + i * 16 + ar;
            af[i][0] = sAl[m][ak];
            af[i][1] = sAl[m + 8][ak];
            af[i][2] = sAl[m][ak + 4];
            af[i][3] = sAl[m + 8][ak + 4];
        }
#pragma unroll
        for (int i = 0; i < 4; i++)
#pragma unroll
            for (int j = 0; j < 4; j++) mma_bf16(acc[i * 4 + j], af[i], bh[j]);
    }

    // epilogue
#pragma unroll
    for (int i = 0; i < 4; i++) {
#pragma unroll
        for (int j = 0; j < 4; j++) {
            int r = row0 + wm + i * 16 + (lane >> 2);
            int c = col0 + wn + j * 8 + (lane & 3) * 2;
            float* ap = acc[i * 4 + j];
#pragma unroll
            for (int h = 0; h < 2; h++) {
                int rr = r + h * 8;
                if (rr >= Nrows) continue;
                float v0 = ap[h * 2 + 0] + bias[c];
                float v1 = ap[h * 2 + 1] + bias[c + 1];
                if (gamma != nullptr) {
                    v0 = gamma[c] * (v0 * bn_inv) + beta[c];
                    v1 = gamma[c + 1] * (v1 * bn_inv) + beta[c + 1];
                }
                if (ACT == 1) { v0 = leaky1(v0); v1 = leaky1(v1); }
                else if (ACT == 2) { v0 = dleaky(v0); v1 = dleaky(v1); }
                *(float2*)&Cmat[(size_t)rr * ldc + c] = make_float2(v0, v1);
            }
        }
    }
}

// ---------------------------------------------------------------------------
// Pooling
// ---------------------------------------------------------------------------
__global__ void zero_pool_kernel() {
    int idx = blockIdx.x * blockDim.x + threadIdx.x;
    if (idx < NMOL * 128 / 4)
        *(float4*)&g_pool[idx * 4] = make_float4(0.f, 0.f, 0.f, 0.f);
}

__global__ void pool_kernel(const int* __restrict__ batch) {
    int idx = blockIdx.x * blockDim.x + threadIdx.x;
    int n = idx >> 5;
    if (n >= NN) return;
    int c4 = (idx & 31) << 2;
    float4 v = *(const float4*)&g_HS[(size_t)n * HSW + 384 + c4];
    float* p = g_pool + (size_t)batch[n] * 128 + c4;
    asm volatile("red.global.add.v4.f32 [%0], {%1,%2,%3,%4};"
                 :: "l"(p), "f"(v.x), "f"(v.y), "f"(v.z), "f"(v.w) : "memory");
}

__global__ void bcast_kernel(const int* __restrict__ batch) {
    int idx = blockIdx.x * blockDim.x + threadIdx.x;
    int n = idx >> 5;
    if (n >= NN) return;
    int c4 = (idx & 31) << 2;
    float4 v = *(const float4*)&g_pool[(size_t)batch[n] * 128 + c4];
    *(float4*)&g_HS[(size_t)n * HSW + 512 + c4] = v;
}

// ---------------------------------------------------------------------------
// Final: out[n] = sigmoid(Z1[n,:] . fW + fb)
// ---------------------------------------------------------------------------
__global__ void final_kernel(const float* __restrict__ Z,
                             const float* __restrict__ fW,
                             const float* __restrict__ fb,
                             float* __restrict__ out) {
    int idx = blockIdx.x * blockDim.x + threadIdx.x;
    int n = idx >> 5;
    if (n >= NN) return;
    int lane = idx & 31;
    float s = 0.f;
#pragma unroll
    for (int j = lane; j < CLSD; j += 32)
        s = fmaf(Z[(size_t)n * CLSD + j], fW[j], s);
#pragma unroll
    for (int o = 16; o; o >>= 1) s += __shfl_xor_sync(0xffffffffu, s, o);
    if (lane == 0) {
        float z = s + fb[0];
        out[n] = 1.f / (1.f + expf(-z));
    }
}

// ---------------------------------------------------------------------------
// Launch
// ---------------------------------------------------------------------------
extern "C" void kernel_launch(void* const* d_in, const int* in_sizes, int n_in,
                              void* d_out, int out_size) {
    const float* x    = (const float*)d_in[0];
    const int*   ei   = (const int*)d_in[1];
    const float* attr = (const float*)d_in[2];
    const int*   batch= (const int*)d_in[3];
    const float* c1W  = (const float*)d_in[4];
    const float* c1b  = (const float*)d_in[5];
    const float* c1g  = (const float*)d_in[6];
    const float* c1be = (const float*)d_in[7];
    const float* c1eW = (const float*)d_in[8];
    const float* c1eb = (const float*)d_in[9];
    const float* cW   = (const float*)d_in[10];
    const float* cb   = (const float*)d_in[11];
    const float* cg   = (const float*)d_in[12];
    const float* cbe  = (const float*)d_in[13];
    const float* ceW  = (const float*)d_in[14];
    const float* ceb  = (const float*)d_in[15];
    const float* k1W  = (const float*)d_in[16];
    const float* k1b  = (const float*)d_in[17];
    const float* kW   = (const float*)d_in[18];
    const float* kb   = (const float*)d_in[19];
    const float* fW   = (const float*)d_in[20];
    const float* fb   = (const float*)d_in[21];
    float* out = (float*)d_out;

    const int* srcp = ei;
    const int* dstp = ei + EE;

    const float bn_inv = (float)(1.0 / (double)((float)sqrt(1.0 + 1e-5)));

    float *agg, *h0, *HS, *z1, *z2;
    unsigned *Bh, *Bl;
    cudaGetSymbolAddress((void**)&agg, g_agg);
    cudaGetSymbolAddress((void**)&h0,  g_h0);
    cudaGetSymbolAddress((void**)&HS,  g_HS);
    cudaGetSymbolAddress((void**)&z1,  g_z1);
    cudaGetSymbolAddress((void**)&z2,  g_z2);
    cudaGetSymbolAddress((void**)&Bh,  g_Bh);
    cudaGetSymbolAddress((void**)&Bl,  g_Bl);

    // ---- CSR build + weight conversion ----
    wcvt_count_kernel<<<CNT_BLK + WCVT_BLK, 256>>>(dstp, c1W, cW, k1W, kW);
    csr_scan_kernel<<<1, 1024>>>();
    fill_permute_kernel<<<(EE * 4 + 255) / 256, 256>>>(srcp, dstp, attr);

    const int GATHER_BLOCKS = (NN + 3) / 4;    // 4 warps per block, warp per node

    // ---- conv1 (64 -> 128) ----
    {
        gather_kernel<2, false><<<GATHER_BLOCKS, 128>>>(x, INRR, c1eW, c1eb, agg);
        dim3 grid(1, (NN + 127) / 128);
        bf16_gemm<2><<<grid, 256>>>(agg, 64, Bh + WC1_OFF, Bl + WC1_OFF,
                                    c1b, c1g, c1be, h0, 128, NN, 64, 128, bn_inv);
    }

    // ---- conv loop (4 layers, 128 -> 128) ----
    for (int i = 0; i < 4; i++) {
        const float* inPtr = (i == 0) ? h0 : (HS + (size_t)(i - 1) * 128);
        int ldin = (i == 0) ? 128 : HSW;
        gather_kernel<4, true><<<GATHER_BLOCKS, 128>>>(inPtr, ldin,
                                                   ceW + (size_t)i * EDD * OUTD,
                                                   ceb + (size_t)i * OUTD, agg);
        dim3 grid(1, (NN + 127) / 128);
        bf16_gemm<2><<<grid, 256>>>(agg, 128,
                                    Bh + WCV_OFF + (size_t)i * 8192,
                                    Bl + WCV_OFF + (size_t)i * 8192,
                                    cb + (size_t)i * OUTD,
                                    cg + (size_t)i * OUTD,
                                    cbe + (size_t)i * OUTD,
                                    HS + (size_t)i * 128, HSW,
                                    NN, 128, 128, bn_inv);
    }

    // ---- global_add_pool + broadcast ----
    zero_pool_kernel<<<(NMOL * 128 / 4 + 255) / 256, 256>>>();
    pool_kernel<<<(NN * 32 + 255) / 256, 256>>>(batch);
    bcast_kernel<<<(NN * 32 + 255) / 256, 256>>>(batch);

    // ---- classifier ----
    {
        dim3 grid1(CLSD / 128, (NN + 127) / 128);
        bf16_gemm<0><<<grid1, 256>>>(HS, HSW, Bh + WK1_OFF, Bl + WK1_OFF,
                                     k1b, nullptr, nullptr,
                                     z1, CLSD, NN, HSW, CLSD, bn_inv);
        bf16_gemm<1><<<grid1, 256>>>(z1, CLSD, Bh + WK2_OFF, Bl + WK2_OFF,
                                     kb, nullptr, nullptr,
                                     z2, CLSD, NN, CLSD, CLSD, bn_inv);
        bf16_gemm<1><<<grid1, 256>>>(z2, CLSD, Bh + WK3_OFF, Bl + WK3_OFF,
                                     kb + CLSD, nullptr, nullptr,
                                     z1, CLSD, NN, CLSD, CLSD, bn_inv);
    }

    // ---- final dot + sigmoid ----
    final_kernel<<<(NN * 32 + 255) / 256, 256>>>(z1, fW, fb, out);
}

// round 11
// speedup vs baseline: 1.1602x; 1.1602x over previous
#include <cuda_runtime.h>
#include <cuda_bf16.h>
#include <math.h>

// Problem constants
#define NN   50000
#define EE   800000
#define NMOL 2000
#define INRR 64
#define OUTD 128
#define EDD  16
#define CLSD 256
#define HSW  640   // OUT*(L_CONV+1)

// Static scratch (no allocations allowed)
__device__ float g_agg[(size_t)NN * 128];
__device__ float g_h0[(size_t)NN * 128];
__device__ float g_HS[(size_t)NN * HSW];
__device__ float g_pool[(size_t)NMOL * 128];
__device__ float g_z1[(size_t)NN * CLSD];
__device__ float g_z2[(size_t)NN * CLSD];
// CSR (by dst) — g_cnt zero at load; csr_scan re-zeroes it each call.
__device__ int g_cnt[NN];
__device__ int g_off[NN + 1];
__device__ int g_cur[NN];
__device__ int g_srcs[EE];                       // CSR-ordered src node
__device__ float g_attrs[(size_t)EE * 16];       // CSR-ordered edge_attr

// Pre-converted packed bf16 weights (hi/lo split).
#define WC1_OFF   0                 // conv1W:  Kp=32,  M=128 -> 4096
#define WCV_OFF   4096              // convW i: Kp=64,  M=128 -> 8192 each (x4)
#define WK1_OFF   36864             // cls1W:   Kp=320, M=256 -> 81920
#define WK2_OFF   118784            // kW[0]:   Kp=128, M=256 -> 32768
#define WK3_OFF   151552            // kW[1]:   Kp=128, M=256 -> 32768
#define WTOT      184320
__device__ unsigned g_Bh[WTOT];
__device__ unsigned g_Bl[WTOT];

__device__ __forceinline__ float dleaky(float v) {
    float t = v > 0.f ? v : 0.01f * v;
    return t > 0.f ? t : 0.01f * t;
}
__device__ __forceinline__ float leaky1(float v) {
    return v > 0.f ? v : 0.01f * v;
}

// f32x2 helpers
__device__ __forceinline__ unsigned long long packf2(float lo, float hi) {
    unsigned long long r;
    asm("mov.b64 %0, {%1, %2};" : "=l"(r) : "r"(__float_as_uint(lo)), "r"(__float_as_uint(hi)));
    return r;
}
__device__ __forceinline__ unsigned long long dupf2(float v) {
    unsigned long long r;
    unsigned b = __float_as_uint(v);
    asm("mov.b64 %0, {%1, %1};" : "=l"(r) : "r"(b));
    return r;
}
__device__ __forceinline__ void fma2(unsigned long long& d,
                                     unsigned long long a, unsigned long long b) {
    asm("fma.rn.f32x2 %0, %1, %2, %0;" : "+l"(d) : "l"(a), "l"(b));
}
__device__ __forceinline__ void unpackf2(unsigned long long v, float& lo, float& hi) {
    unsigned ulo, uhi;
    asm("mov.b64 {%0, %1}, %2;" : "=r"(ulo), "=r"(uhi) : "l"(v));
    lo = __uint_as_float(ulo);
    hi = __uint_as_float(uhi);
}

__device__ __forceinline__ unsigned pack_bf16(float lo, float hi) {
    __nv_bfloat162 h = __floats2bfloat162_rn(lo, hi);
    return *(unsigned*)&h;
}

// ---------------------------------------------------------------------------
// Fused: blocks [0, CNT_BLK) count edge dst; rest convert weights to bf16 hi/lo
// ---------------------------------------------------------------------------
#define CNT_BLK 3125                 // ceil(EE/256)
#define WCVT_BLK 720                 // ceil(WTOT/256)

__global__ void wcvt_count_kernel(const int* __restrict__ dstv,
                                  const float* __restrict__ c1W,
                                  const float* __restrict__ cW,
                                  const float* __restrict__ k1W,
                                  const float* __restrict__ kW) {
    if (blockIdx.x < CNT_BLK) {
        int e = blockIdx.x * blockDim.x + threadIdx.x;
        if (e < EE) atomicAdd(&g_cnt[dstv[e]], 1);
        return;
    }
    int widx = (blockIdx.x - CNT_BLK) * blockDim.x + threadIdx.x;
    if (widx >= WTOT) return;
    const float* src;
    int M, kp, m;
    if (widx < WCV_OFF) {
        src = c1W; M = 128;
        kp = widx >> 7; m = widx & 127;
    } else if (widx < WK1_OFF) {
        int r = widx - WCV_OFF;
        int i = r >> 13; r &= 8191;
        src = cW + (size_t)i * OUTD * OUTD; M = 128;
        kp = r >> 7; m = r & 127;
    } else if (widx < WK2_OFF) {
        int r = widx - WK1_OFF;
        src = k1W; M = 256;
        kp = r >> 8; m = r & 255;
    } else if (widx < WK3_OFF) {
        int r = widx - WK2_OFF;
        src = kW; M = 256;
        kp = r >> 8; m = r & 255;
    } else {
        int r = widx - WK3_OFF;
        src = kW + CLSD * CLSD; M = 256;
        kp = r >> 8; m = r & 255;
    }
    float v0 = src[(size_t)(2 * kp) * M + m];
    float v1 = src[(size_t)(2 * kp + 1) * M + m];
    float h0 = __bfloat162float(__float2bfloat16(v0));
    float h1 = __bfloat162float(__float2bfloat16(v1));
    g_Bh[widx] = pack_bf16(h0, h1);
    g_Bl[widx] = pack_bf16(v0 - h0, v1 - h1);
}

// ---------------------------------------------------------------------------
// Scan: g_cnt -> g_off/g_cur, then zero g_cnt
// ---------------------------------------------------------------------------
__global__ void csr_scan_kernel() {
    __shared__ int part[1024];
    const int CH = (NN + 1023) / 1024;
    int t = threadIdx.x;
    int start = t * CH;
    int sum = 0;
    for (int i = 0; i < CH; i++) {
        int idx = start + i;
        if (idx < NN) sum += g_cnt[idx];
    }
    part[t] = sum;
    __syncthreads();
    for (int o = 1; o < 1024; o <<= 1) {
        int v = (t >= o) ? part[t - o] : 0;
        __syncthreads();
        part[t] += v;
        __syncthreads();
    }
    int run = part[t] - sum;
    for (int i = 0; i < CH; i++) {
        int idx = start + i;
        if (idx < NN) {
            g_off[idx] = run;
            g_cur[idx] = run;
            run += g_cnt[idx];
            g_cnt[idx] = 0;
        }
    }
    if (t == 0) g_off[NN] = EE;
}

// ---------------------------------------------------------------------------
// Fill + permute fused: 4 threads per edge.
// ---------------------------------------------------------------------------
__global__ void fill_permute_kernel(const int* __restrict__ srcv,
                                    const int* __restrict__ dstv,
                                    const float* __restrict__ attr) {
    int idx = blockIdx.x * blockDim.x + threadIdx.x;   // EE*4
    if (idx >= EE * 4) return;
    int e = idx >> 2, c4 = idx & 3;
    int lane = threadIdx.x & 31;
    int pos = 0;
    if (c4 == 0) pos = atomicAdd(&g_cur[dstv[e]], 1);
    pos = __shfl_sync(0xffffffffu, pos, lane & ~3);
    float4 v = __ldg((const float4*)&attr[(size_t)e * 16 + c4 * 4]);
    *(float4*)&g_attrs[(size_t)pos * 16 + c4 * 4] = v;
    if (c4 == 0) g_srcs[pos] = __ldg(&srcv[e]);
}

// ---------------------------------------------------------------------------
// Gather with cp.async smem ring — the PROVEN C=2 shape for all layers.
// WPN warps per node; each warp owns a fixed 64-column half (2 floats/lane),
// edge-MLP weights (16 f32x2 words) in REGISTERS, 6-edge lookahead ring.
//   agg[n] = x[n] + sum_{e: dst=n} relu(x[src[e]] + attr[e]@eW + eb)
// ---------------------------------------------------------------------------
template <int WPN>
__global__ __launch_bounds__(128, 8)
void gather_kernel(const float* __restrict__ x, int ldx,
                   const float* __restrict__ eW,
                   const float* __restrict__ eb,
                   float* __restrict__ agg) {
    constexpr int D = WPN * 64;        // agg row width
    constexpr int XB = 256;            // x-half bytes per warp (32 lanes x 8B)
    constexpr int SLOT = XB + 64;      // + attr
    constexpr int NS = 8;              // ring slots (power of 2)
    constexpr int LA = 6;              // lookahead depth

    __shared__ __align__(16) char s_ring[4 * NS * SLOT];

    const int tid = threadIdx.x;
    const int lane = tid & 31;
    const int wIn = tid >> 5;
    char* ring = s_ring + wIn * (NS * SLOT);

    const int gw = (blockIdx.x * blockDim.x + tid) >> 5;
    const int n = gw / WPN;
    const int half = gw - n * WPN;
    if (n >= NN) return;
    const int col = half * 64 + lane * 2;

    // weights in registers: 16 f32x2 words
    unsigned long long wp[16];
#pragma unroll
    for (int k = 0; k < 16; k++)
        wp[k] = packf2(eW[k * D + col], eW[k * D + col + 1]);
    unsigned long long ebp = packf2(eb[col], eb[col + 1]);

    const int i0 = __ldg(&g_off[n]);
    const int i1 = __ldg(&g_off[n + 1]);

    float acc0, acc1;
    {
        float2 xv = *(const float2*)&x[(size_t)n * ldx + col];
        acc0 = xv.x; acc1 = xv.y;
    }

    auto issue = [&](int pos, int s) {
        if (pos < i1) {
            char* sp = ring + (pos & (NS - 1)) * SLOT;
            const float* grow = x + (size_t)s * ldx + col;
            unsigned sx = (unsigned)__cvta_generic_to_shared(sp) + lane * 8;
            asm volatile("cp.async.ca.shared.global [%0], [%1], 8;"
                         :: "r"(sx), "l"(grow));
            if (lane < 4) {
                const float* ga = g_attrs + (size_t)pos * 16 + lane * 4;
                unsigned sa = (unsigned)__cvta_generic_to_shared(sp) + XB + lane * 16;
                asm volatile("cp.async.ca.shared.global [%0], [%1], 16;"
                             :: "r"(sa), "l"(ga));
            }
        }
        asm volatile("cp.async.commit_group;" ::: "memory");
    };

    // prologue: issue LA edges (src prefetched one ahead)
    int s_pf = (i0 < i1) ? __ldg(&g_srcs[i0]) : 0;
#pragma unroll
    for (int j = 0; j < LA; j++) {
        int p = i0 + j;
        int s_nx = (p + 1 < i1) ? __ldg(&g_srcs[p + 1]) : 0;
        issue(p, s_pf);
        s_pf = s_nx;
    }

    for (int pos = i0; pos < i1; pos++) {
        int p = pos + LA;
        int s_nx = (p + 1 < i1) ? __ldg(&g_srcs[p + 1]) : 0;
        issue(p, s_pf);
        s_pf = s_nx;

        asm volatile("cp.async.wait_group 6;" ::: "memory");
        __syncwarp();

        const char* sp = ring + (pos & (NS - 1)) * SLOT;
        const float4* ap = (const float4*)(sp + XB);
        float4 A0 = ap[0], A1 = ap[1], A2 = ap[2], A3 = ap[3];
        float av[16] = {A0.x, A0.y, A0.z, A0.w, A1.x, A1.y, A1.z, A1.w,
                        A2.x, A2.y, A2.z, A2.w, A3.x, A3.y, A3.z, A3.w};
        unsigned long long e = ebp;
#pragma unroll
        for (int k = 0; k < 16; k++) fma2(e, dupf2(av[k]), wp[k]);
        float lo, hi;
        unpackf2(e, lo, hi);
        float2 xr = *(const float2*)(sp + lane * 8);
        float m0 = xr.x + lo;
        float m1 = xr.y + hi;
        acc0 += m0 > 0.f ? m0 : 0.f;
        acc1 += m1 > 0.f ? m1 : 0.f;
    }

    *(float2*)&g_agg[(size_t)n * D + col] = make_float2(acc0, acc1);
}

// ---------------------------------------------------------------------------
// Split-bf16 tensor-core GEMM with pre-converted packed B.
// ---------------------------------------------------------------------------
__device__ __forceinline__ void mma_bf16(float* acc, const unsigned* a, const unsigned* b) {
    asm volatile(
        "mma.sync.aligned.m16n8k16.row.col.f32.bf16.bf16.f32 "
        "{%0,%1,%2,%3}, {%4,%5,%6,%7}, {%8,%9}, {%0,%1,%2,%3};"
        : "+f"(acc[0]), "+f"(acc[1]), "+f"(acc[2]), "+f"(acc[3])
        : "r"(a[0]), "r"(a[1]), "r"(a[2]), "r"(a[3]), "r"(b[0]), "r"(b[1]));
}

template <int ACT>
__global__ __launch_bounds__(256)
void bf16_gemm(const float* __restrict__ A, int lda,
               const unsigned* __restrict__ PBh,
               const unsigned* __restrict__ PBl,
               const float* __restrict__ bias,
               const float* __restrict__ gamma,
               const float* __restrict__ beta,
               float* __restrict__ Cmat, int ldc,
               int Nrows, int K, int M, float bn_inv) {
    __shared__ unsigned sAh[128][9];
    __shared__ unsigned sAl[128][9];
    __shared__ unsigned sBh[128][9];
    __shared__ unsigned sBl[128][9];

    const int tid = threadIdx.x;
    const int lane = tid & 31;
    const int wid = tid >> 5;
    const int wm = (wid & 1) * 64;
    const int wn = (wid >> 1) * 32;
    const int row0 = blockIdx.y * 128;
    const int col0 = blockIdx.x * 128;

    float acc[16][4];
#pragma unroll
    for (int i = 0; i < 16; i++)
#pragma unroll
        for (int j = 0; j < 4; j++) acc[i][j] = 0.f;

    float4 ga[2];
    uint2 gh[2], gl[2];

    auto load_tile = [&](int k0) {
#pragma unroll
        for (int j = 0; j < 2; j++) {
            int idx = j * 256 + tid;
            int m = idx >> 2, kk = (idx & 3) << 2;
            int r = row0 + m;
            ga[j] = make_float4(0.f, 0.f, 0.f, 0.f);
            if (r < Nrows) ga[j] = *(const float4*)&A[(size_t)r * lda + k0 + kk];
            int n = (idx & 63) << 1, bkp = idx >> 6;
            size_t off = (size_t)(k0 / 2 + bkp) * M + col0 + n;
            gh[j] = *(const uint2*)&PBh[off];
            gl[j] = *(const uint2*)&PBl[off];
        }
    };

    load_tile(0);

    for (int k0 = 0; k0 < K; k0 += 16) {
        __syncthreads();
#pragma unroll
        for (int j = 0; j < 2; j++) {
            int idx = j * 256 + tid;
            int m = idx >> 2, kp = (idx & 3) << 1;
            float4 v = ga[j];
            float hx = __bfloat162float(__float2bfloat16(v.x));
            float hy = __bfloat162float(__float2bfloat16(v.y));
            float hz = __bfloat162float(__float2bfloat16(v.z));
            float hw = __bfloat162float(__float2bfloat16(v.w));
            sAh[m][kp]     = pack_bf16(hx, hy);
            sAh[m][kp + 1] = pack_bf16(hz, hw);
            sAl[m][kp]     = pack_bf16(v.x - hx, v.y - hy);
            sAl[m][kp + 1] = pack_bf16(v.z - hz, v.w - hw);

            int n = (idx & 63) << 1, bkp = idx >> 6;
            sBh[n][bkp]     = gh[j].x;
            sBh[n + 1][bkp] = gh[j].y;
            sBl[n][bkp]     = gl[j].x;
            sBl[n + 1][bkp] = gl[j].y;
        }
        __syncthreads();

        if (k0 + 16 < K) load_tile(k0 + 16);

        unsigned af[4][4], bh[4][2], bl[4][2];
        const int ar = lane >> 2, ak = lane & 3;
#pragma unroll
        for (int i = 0; i < 4; i++) {
            int m = wm + i * 16 + ar;
            af[i][0] = sAh[m][ak];
            af[i][1] = sAh[m + 8][ak];
            af[i][2] = sAh[m][ak + 4];
            af[i][3] = sAh[m + 8][ak + 4];
        }
#pragma unroll
        for (int j = 0; j < 4; j++) {
            int nn = wn + j * 8 + (lane >> 2);
            bh[j][0] = sBh[nn][lane & 3];
            bh[j][1] = sBh[nn][(lane & 3) + 4];
            bl[j][0] = sBl[nn][lane & 3];
            bl[j][1] = sBl[nn][(lane & 3) + 4];
        }
#pragma unroll
        for (int i = 0; i < 4; i++)
#pragma unroll
            for (int j = 0; j < 4; j++) mma_bf16(acc[i * 4 + j], af[i], bh[j]);
#pragma unroll
        for (int i = 0; i < 4; i++)
#pragma unroll
            for (int j = 0; j < 4; j++) mma_bf16(acc[i * 4 + j], af[i], bl[j]);
#pragma unroll
        for (int i = 0; i < 4; i++) {
            int m = wm + i * 16 + ar;
            af[i][0] = sAl[m][ak];
            af[i][1] = sAl[m + 8][ak];
            af[i][2] = sAl[m][ak + 4];
            af[i][3] = sAl[m + 8][ak + 4];
        }
#pragma unroll
        for (int i = 0; i < 4; i++)
#pragma unroll
            for (int j = 0; j < 4; j++) mma_bf16(acc[i * 4 + j], af[i], bh[j]);
    }

    // epilogue
#pragma unroll
    for (int i = 0; i < 4; i++) {
#pragma unroll
        for (int j = 0; j < 4; j++) {
            int r = row0 + wm + i * 16 + (lane >> 2);
            int c = col0 + wn + j * 8 + (lane & 3) * 2;
            float* ap = acc[i * 4 + j];
#pragma unroll
            for (int h = 0; h < 2; h++) {
                int rr = r + h * 8;
                if (rr >= Nrows) continue;
                float v0 = ap[h * 2 + 0] + bias[c];
                float v1 = ap[h * 2 + 1] + bias[c + 1];
                if (gamma != nullptr) {
                    v0 = gamma[c] * (v0 * bn_inv) + beta[c];
                    v1 = gamma[c + 1] * (v1 * bn_inv) + beta[c + 1];
                }
                if (ACT == 1) { v0 = leaky1(v0); v1 = leaky1(v1); }
                else if (ACT == 2) { v0 = dleaky(v0); v1 = dleaky(v1); }
                *(float2*)&Cmat[(size_t)rr * ldc + c] = make_float2(v0, v1);
            }
        }
    }
}

// ---------------------------------------------------------------------------
// Pooling
// ---------------------------------------------------------------------------
__global__ void zero_pool_kernel() {
    int idx = blockIdx.x * blockDim.x + threadIdx.x;
    if (idx < NMOL * 128 / 4)
        *(float4*)&g_pool[idx * 4] = make_float4(0.f, 0.f, 0.f, 0.f);
}

__global__ void pool_kernel(const int* __restrict__ batch) {
    int idx = blockIdx.x * blockDim.x + threadIdx.x;
    int n = idx >> 5;
    if (n >= NN) return;
    int c4 = (idx & 31) << 2;
    float4 v = *(const float4*)&g_HS[(size_t)n * HSW + 384 + c4];
    float* p = g_pool + (size_t)batch[n] * 128 + c4;
    asm volatile("red.global.add.v4.f32 [%0], {%1,%2,%3,%4};"
                 :: "l"(p), "f"(v.x), "f"(v.y), "f"(v.z), "f"(v.w) : "memory");
}

__global__ void bcast_kernel(const int* __restrict__ batch) {
    int idx = blockIdx.x * blockDim.x + threadIdx.x;
    int n = idx >> 5;
    if (n >= NN) return;
    int c4 = (idx & 31) << 2;
    float4 v = *(const float4*)&g_pool[(size_t)batch[n] * 128 + c4];
    *(float4*)&g_HS[(size_t)n * HSW + 512 + c4] = v;
}

// ---------------------------------------------------------------------------
// Final: out[n] = sigmoid(Z1[n,:] . fW + fb)
// ---------------------------------------------------------------------------
__global__ void final_kernel(const float* __restrict__ Z,
                             const float* __restrict__ fW,
                             const float* __restrict__ fb,
                             float* __restrict__ out) {
    int idx = blockIdx.x * blockDim.x + threadIdx.x;
    int n = idx >> 5;
    if (n >= NN) return;
    int lane = idx & 31;
    float s = 0.f;
#pragma unroll
    for (int j = lane; j < CLSD; j += 32)
        s = fmaf(Z[(size_t)n * CLSD + j], fW[j], s);
#pragma unroll
    for (int o = 16; o; o >>= 1) s += __shfl_xor_sync(0xffffffffu, s, o);
    if (lane == 0) {
        float z = s + fb[0];
        out[n] = 1.f / (1.f + expf(-z));
    }
}

// ---------------------------------------------------------------------------
// Launch
// ---------------------------------------------------------------------------
extern "C" void kernel_launch(void* const* d_in, const int* in_sizes, int n_in,
                              void* d_out, int out_size) {
    const float* x    = (const float*)d_in[0];
    const int*   ei   = (const int*)d_in[1];
    const float* attr = (const float*)d_in[2];
    const int*   batch= (const int*)d_in[3];
    const float* c1W  = (const float*)d_in[4];
    const float* c1b  = (const float*)d_in[5];
    const float* c1g  = (const float*)d_in[6];
    const float* c1be = (const float*)d_in[7];
    const float* c1eW = (const float*)d_in[8];
    const float* c1eb = (const float*)d_in[9];
    const float* cW   = (const float*)d_in[10];
    const float* cb   = (const float*)d_in[11];
    const float* cg   = (const float*)d_in[12];
    const float* cbe  = (const float*)d_in[13];
    const float* ceW  = (const float*)d_in[14];
    const float* ceb  = (const float*)d_in[15];
    const float* k1W  = (const float*)d_in[16];
    const float* k1b  = (const float*)d_in[17];
    const float* kW   = (const float*)d_in[18];
    const float* kb   = (const float*)d_in[19];
    const float* fW   = (const float*)d_in[20];
    const float* fb   = (const float*)d_in[21];
    float* out = (float*)d_out;

    const int* srcp = ei;
    const int* dstp = ei + EE;

    const float bn_inv = (float)(1.0 / (double)((float)sqrt(1.0 + 1e-5)));

    float *agg, *h0, *HS, *z1, *z2;
    unsigned *Bh, *Bl;
    cudaGetSymbolAddress((void**)&agg, g_agg);
    cudaGetSymbolAddress((void**)&h0,  g_h0);
    cudaGetSymbolAddress((void**)&HS,  g_HS);
    cudaGetSymbolAddress((void**)&z1,  g_z1);
    cudaGetSymbolAddress((void**)&z2,  g_z2);
    cudaGetSymbolAddress((void**)&Bh,  g_Bh);
    cudaGetSymbolAddress((void**)&Bl,  g_Bl);

    // ---- CSR build + weight conversion ----
    wcvt_count_kernel<<<CNT_BLK + WCVT_BLK, 256>>>(dstp, c1W, cW, k1W, kW);
    csr_scan_kernel<<<1, 1024>>>();
    fill_permute_kernel<<<(EE * 4 + 255) / 256, 256>>>(srcp, dstp, attr);

    // ---- conv1 (64 -> 128): 1 warp per node ----
    {
        gather_kernel<1><<<(NN + 3) / 4, 128>>>(x, INRR, c1eW, c1eb, agg);
        dim3 grid(1, (NN + 127) / 128);
        bf16_gemm<2><<<grid, 256>>>(agg, 64, Bh + WC1_OFF, Bl + WC1_OFF,
                                    c1b, c1g, c1be, h0, 128, NN, 64, 128, bn_inv);
    }

    // ---- conv loop (4 layers, 128 -> 128): 2 warps per node, C=2 each ----
    for (int i = 0; i < 4; i++) {
        const float* inPtr = (i == 0) ? h0 : (HS + (size_t)(i - 1) * 128);
        int ldin = (i == 0) ? 128 : HSW;
        gather_kernel<2><<<(NN * 2 + 3) / 4, 128>>>(inPtr, ldin,
                                                   ceW + (size_t)i * EDD * OUTD,
                                                   ceb + (size_t)i * OUTD, agg);
        dim3 grid(1, (NN + 127) / 128);
        bf16_gemm<2><<<grid, 256>>>(agg, 128,
                                    Bh + WCV_OFF + (size_t)i * 8192,
                                    Bl + WCV_OFF + (size_t)i * 8192,
                                    cb + (size_t)i * OUTD,
                                    cg + (size_t)i * OUTD,
                                    cbe + (size_t)i * OUTD,
                                    HS + (size_t)i * 128, HSW,
                                    NN, 128, 128, bn_inv);
    }

    // ---- global_add_pool + broadcast ----
    zero_pool_kernel<<<(NMOL * 128 / 4 + 255) / 256, 256>>>();
    pool_kernel<<<(NN * 32 + 255) / 256, 256>>>(batch);
    bcast_kernel<<<(NN * 32 + 255) / 256, 256>>>(batch);

    // ---- classifier ----
    {
        dim3 grid1(CLSD / 128, (NN + 127) / 128);
        bf16_gemm<0><<<grid1, 256>>>(HS, HSW, Bh + WK1_OFF, Bl + WK1_OFF,
                                     k1b, nullptr, nullptr,
                                     z1, CLSD, NN, HSW, CLSD, bn_inv);
        bf16_gemm<1><<<grid1, 256>>>(z1, CLSD, Bh + WK2_OFF, Bl + WK2_OFF,
                                     kb, nullptr, nullptr,
                                     z2, CLSD, NN, CLSD, CLSD, bn_inv);
        bf16_gemm<1><<<grid1, 256>>>(z2, CLSD, Bh + WK3_OFF, Bl + WK3_OFF,
                                     kb + CLSD, nullptr, nullptr,
                                     z1, CLSD, NN, CLSD, CLSD, bn_inv);
    }

    // ---- final dot + sigmoid ----
    final_kernel<<<(NN * 32 + 255) / 256, 256>>>(z1, fW, fb, out);
}

// round 12
// speedup vs baseline: 1.2425x; 1.0709x over previous
#include <cuda_runtime.h>
#include <cuda_bf16.h>
#include <math.h>

// Problem constants
#define NN   50000
#define EE   800000
#define NMOL 2000
#define INRR 64
#define OUTD 128
#define EDD  16
#define CLSD 256
#define HSW  640   // OUT*(L_CONV+1)

// Static scratch (no allocations allowed)
__device__ float g_agg[(size_t)NN * 128];
__device__ float g_h0[(size_t)NN * 128];
__device__ float g_HS[(size_t)NN * HSW];
__device__ float g_pool[(size_t)NMOL * 128];
__device__ float g_z1[(size_t)NN * CLSD];
__device__ float g_z2[(size_t)NN * CLSD];
// CSR (by dst) — g_cnt zero at load; csr_scan re-zeroes it each call.
__device__ int g_cnt[NN];
__device__ int g_off[NN + 1];
__device__ int g_cur[NN];
__device__ int g_srcs[EE];                       // CSR-ordered src node
__device__ float g_attrs[(size_t)EE * 16];       // CSR-ordered edge_attr

// Pre-converted packed bf16 weights (hi/lo split).
#define WC1_OFF   0                 // conv1W:  Kp=32,  M=128 -> 4096
#define WCV_OFF   4096              // convW i: Kp=64,  M=128 -> 8192 each (x4)
#define WK1_OFF   36864             // cls1W:   Kp=320, M=256 -> 81920
#define WK2_OFF   118784            // kW[0]:   Kp=128, M=256 -> 32768
#define WK3_OFF   151552            // kW[1]:   Kp=128, M=256 -> 32768
#define WTOT      184320
__device__ unsigned g_Bh[WTOT];
__device__ unsigned g_Bl[WTOT];

__device__ __forceinline__ float dleaky(float v) {
    float t = v > 0.f ? v : 0.01f * v;
    return t > 0.f ? t : 0.01f * t;
}
__device__ __forceinline__ float leaky1(float v) {
    return v > 0.f ? v : 0.01f * v;
}

// f32x2 helpers
__device__ __forceinline__ unsigned long long packf2(float lo, float hi) {
    unsigned long long r;
    asm("mov.b64 %0, {%1, %2};" : "=l"(r) : "r"(__float_as_uint(lo)), "r"(__float_as_uint(hi)));
    return r;
}
__device__ __forceinline__ unsigned long long dupf2(float v) {
    unsigned long long r;
    unsigned b = __float_as_uint(v);
    asm("mov.b64 %0, {%1, %1};" : "=l"(r) : "r"(b));
    return r;
}
__device__ __forceinline__ void fma2(unsigned long long& d,
                                     unsigned long long a, unsigned long long b) {
    asm("fma.rn.f32x2 %0, %1, %2, %0;" : "+l"(d) : "l"(a), "l"(b));
}
__device__ __forceinline__ void unpackf2(unsigned long long v, float& lo, float& hi) {
    unsigned ulo, uhi;
    asm("mov.b64 {%0, %1}, %2;" : "=r"(ulo), "=r"(uhi) : "l"(v));
    lo = __uint_as_float(ulo);
    hi = __uint_as_float(uhi);
}

__device__ __forceinline__ unsigned pack_bf16(float lo, float hi) {
    __nv_bfloat162 h = __floats2bfloat162_rn(lo, hi);
    return *(unsigned*)&h;
}

// ---------------------------------------------------------------------------
// Fused: blocks [0, CNT_BLK) count edge dst; rest convert weights to bf16 hi/lo
// ---------------------------------------------------------------------------
#define CNT_BLK 3125                 // ceil(EE/256)
#define WCVT_BLK 720                 // ceil(WTOT/256)

__global__ void wcvt_count_kernel(const int* __restrict__ dstv,
                                  const float* __restrict__ c1W,
                                  const float* __restrict__ cW,
                                  const float* __restrict__ k1W,
                                  const float* __restrict__ kW) {
    if (blockIdx.x < CNT_BLK) {
        int e = blockIdx.x * blockDim.x + threadIdx.x;
        if (e < EE) atomicAdd(&g_cnt[dstv[e]], 1);
        return;
    }
    int widx = (blockIdx.x - CNT_BLK) * blockDim.x + threadIdx.x;
    if (widx >= WTOT) return;
    const float* src;
    int M, kp, m;
    if (widx < WCV_OFF) {
        src = c1W; M = 128;
        kp = widx >> 7; m = widx & 127;
    } else if (widx < WK1_OFF) {
        int r = widx - WCV_OFF;
        int i = r >> 13; r &= 8191;
        src = cW + (size_t)i * OUTD * OUTD; M = 128;
        kp = r >> 7; m = r & 127;
    } else if (widx < WK2_OFF) {
        int r = widx - WK1_OFF;
        src = k1W; M = 256;
        kp = r >> 8; m = r & 255;
    } else if (widx < WK3_OFF) {
        int r = widx - WK2_OFF;
        src = kW; M = 256;
        kp = r >> 8; m = r & 255;
    } else {
        int r = widx - WK3_OFF;
        src = kW + CLSD * CLSD; M = 256;
        kp = r >> 8; m = r & 255;
    }
    float v0 = src[(size_t)(2 * kp) * M + m];
    float v1 = src[(size_t)(2 * kp + 1) * M + m];
    float h0 = __bfloat162float(__float2bfloat16(v0));
    float h1 = __bfloat162float(__float2bfloat16(v1));
    g_Bh[widx] = pack_bf16(h0, h1);
    g_Bl[widx] = pack_bf16(v0 - h0, v1 - h1);
}

// ---------------------------------------------------------------------------
// Scan: g_cnt -> g_off/g_cur, then zero g_cnt
// ---------------------------------------------------------------------------
__global__ void csr_scan_kernel() {
    __shared__ int part[1024];
    const int CH = (NN + 1023) / 1024;
    int t = threadIdx.x;
    int start = t * CH;
    int sum = 0;
    for (int i = 0; i < CH; i++) {
        int idx = start + i;
        if (idx < NN) sum += g_cnt[idx];
    }
    part[t] = sum;
    __syncthreads();
    for (int o = 1; o < 1024; o <<= 1) {
        int v = (t >= o) ? part[t - o] : 0;
        __syncthreads();
        part[t] += v;
        __syncthreads();
    }
    int run = part[t] - sum;
    for (int i = 0; i < CH; i++) {
        int idx = start + i;
        if (idx < NN) {
            g_off[idx] = run;
            g_cur[idx] = run;
            run += g_cnt[idx];
            g_cnt[idx] = 0;
        }
    }
    if (t == 0) g_off[NN] = EE;
}

// ---------------------------------------------------------------------------
// Fill + permute fused: 4 threads per edge.
// ---------------------------------------------------------------------------
__global__ void fill_permute_kernel(const int* __restrict__ srcv,
                                    const int* __restrict__ dstv,
                                    const float* __restrict__ attr) {
    int idx = blockIdx.x * blockDim.x + threadIdx.x;   // EE*4
    if (idx >= EE * 4) return;
    int e = idx >> 2, c4 = idx & 3;
    int lane = threadIdx.x & 31;
    int pos = 0;
    if (c4 == 0) pos = atomicAdd(&g_cur[dstv[e]], 1);
    pos = __shfl_sync(0xffffffffu, pos, lane & ~3);
    float4 v = __ldg((const float4*)&attr[(size_t)e * 16 + c4 * 4]);
    *(float4*)&g_attrs[(size_t)pos * 16 + c4 * 4] = v;
    if (c4 == 0) g_srcs[pos] = __ldg(&srcv[e]);
}

// ---------------------------------------------------------------------------
// Gather with cp.async smem ring, 2-edge commit groups (amortized wait/sync).
// WPN warps per node; each warp owns a fixed 64-column half (2 floats/lane),
// edge-MLP weights (16 f32x2 words) in REGISTERS.
//   agg[n] = x[n] + sum_{e: dst=n} relu(x[src[e]] + attr[e]@eW + eb)
// Pipeline: groups of 2 edges, LAG=3 groups (6 edges) lookahead,
// one commit + one wait_group + one syncwarp per 2 edges.
// ---------------------------------------------------------------------------
template <int WPN>
__global__ __launch_bounds__(128, 8)
void gather_kernel(const float* __restrict__ x, int ldx,
                   const float* __restrict__ eW,
                   const float* __restrict__ eb,
                   float* __restrict__ agg) {
    constexpr int D = WPN * 64;        // agg row width
    constexpr int XB = 256;            // x-half bytes per warp (32 lanes x 8B)
    constexpr int SLOT = XB + 64;      // + attr
    constexpr int NS = 8;              // ring slots (edges)
    constexpr int LAG = 3;             // lookahead groups (2 edges each)

    __shared__ __align__(16) char s_ring[4 * NS * SLOT];

    const int tid = threadIdx.x;
    const int lane = tid & 31;
    const int wIn = tid >> 5;
    char* ring = s_ring + wIn * (NS * SLOT);

    const int gw = (blockIdx.x * blockDim.x + tid) >> 5;
    const int n = gw / WPN;
    const int half = gw - n * WPN;
    if (n >= NN) return;
    const int col = half * 64 + lane * 2;

    // weights in registers: 16 f32x2 words
    unsigned long long wp[16];
#pragma unroll
    for (int k = 0; k < 16; k++)
        wp[k] = packf2(eW[k * D + col], eW[k * D + col + 1]);
    unsigned long long ebp = packf2(eb[col], eb[col + 1]);

    const int i0 = __ldg(&g_off[n]);
    const int i1 = __ldg(&g_off[n + 1]);

    float acc0, acc1;
    {
        float2 xv = *(const float2*)&x[(size_t)n * ldx + col];
        acc0 = xv.x; acc1 = xv.y;
    }

    const int T = i1 - i0;
    const int G = (T + 1) >> 1;        // number of 2-edge groups

    auto issue_edge = [&](int pos, int s) {
        if (pos < i1) {
            char* sp = ring + (pos & (NS - 1)) * SLOT;
            const float* grow = x + (size_t)s * ldx + col;
            unsigned sx = (unsigned)__cvta_generic_to_shared(sp) + lane * 8;
            asm volatile("cp.async.ca.shared.global [%0], [%1], 8;"
                         :: "r"(sx), "l"(grow));
            if (lane < 4) {
                const float* ga = g_attrs + (size_t)pos * 16 + lane * 4;
                unsigned sa = (unsigned)__cvta_generic_to_shared(sp) + XB + lane * 16;
                asm volatile("cp.async.ca.shared.global [%0], [%1], 16;"
                             :: "r"(sa), "l"(ga));
            }
        }
    };

    auto ld_srcs2 = [&](int g, int& a, int& b) {
        int p = i0 + 2 * g;
        a = (p < i1) ? __ldg(&g_srcs[p]) : 0;
        b = (p + 1 < i1) ? __ldg(&g_srcs[p + 1]) : 0;
    };

    auto process = [&](int pos) {
        const char* sp = ring + (pos & (NS - 1)) * SLOT;
        const float4* ap = (const float4*)(sp + XB);
        float4 A0 = ap[0], A1 = ap[1], A2 = ap[2], A3 = ap[3];
        float av[16] = {A0.x, A0.y, A0.z, A0.w, A1.x, A1.y, A1.z, A1.w,
                        A2.x, A2.y, A2.z, A2.w, A3.x, A3.y, A3.z, A3.w};
        unsigned long long e = ebp;
#pragma unroll
        for (int k = 0; k < 16; k++) fma2(e, dupf2(av[k]), wp[k]);
        float lo, hi;
        unpackf2(e, lo, hi);
        float2 xr = *(const float2*)(sp + lane * 8);
        float m0 = xr.x + lo;
        float m1 = xr.y + hi;
        acc0 += m0 > 0.f ? m0 : 0.f;
        acc1 += m1 > 0.f ? m1 : 0.f;
    };

    // prologue: issue LAG groups
    int sA, sB;
#pragma unroll
    for (int j = 0; j < LAG; j++) {
        ld_srcs2(j, sA, sB);
        issue_edge(i0 + 2 * j, sA);
        issue_edge(i0 + 2 * j + 1, sB);
        asm volatile("cp.async.commit_group;" ::: "memory");
    }
    ld_srcs2(LAG, sA, sB);             // srcs for next group to issue

    for (int g = 0; g < G; g++) {
        int nA, nB;
        ld_srcs2(g + LAG + 1, nA, nB); // prefetch next group's srcs
        int p = i0 + 2 * (g + LAG);
        issue_edge(p, sA);
        issue_edge(p + 1, sB);
        asm volatile("cp.async.commit_group;" ::: "memory");
        sA = nA; sB = nB;

        asm volatile("cp.async.wait_group 3;" ::: "memory");
        __syncwarp();

        int q = i0 + 2 * g;
        process(q);
        if (q + 1 < i1) process(q + 1);
    }

    *(float2*)&g_agg[(size_t)n * D + col] = make_float2(acc0, acc1);
}

// ---------------------------------------------------------------------------
// Split-bf16 tensor-core GEMM with pre-converted packed B.
// ---------------------------------------------------------------------------
__device__ __forceinline__ void mma_bf16(float* acc, const unsigned* a, const unsigned* b) {
    asm volatile(
        "mma.sync.aligned.m16n8k16.row.col.f32.bf16.bf16.f32 "
        "{%0,%1,%2,%3}, {%4,%5,%6,%7}, {%8,%9}, {%0,%1,%2,%3};"
        : "+f"(acc[0]), "+f"(acc[1]), "+f"(acc[2]), "+f"(acc[3])
        : "r"(a[0]), "r"(a[1]), "r"(a[2]), "r"(a[3]), "r"(b[0]), "r"(b[1]));
}

template <int ACT>
__global__ __launch_bounds__(256)
void bf16_gemm(const float* __restrict__ A, int lda,
               const unsigned* __restrict__ PBh,
               const unsigned* __restrict__ PBl,
               const float* __restrict__ bias,
               const float* __restrict__ gamma,
               const float* __restrict__ beta,
               float* __restrict__ Cmat, int ldc,
               int Nrows, int K, int M, float bn_inv) {
    __shared__ unsigned sAh[128][9];
    __shared__ unsigned sAl[128][9];
    __shared__ unsigned sBh[128][9];
    __shared__ unsigned sBl[128][9];

    const int tid = threadIdx.x;
    const int lane = tid & 31;
    const int wid = tid >> 5;
    const int wm = (wid & 1) * 64;
    const int wn = (wid >> 1) * 32;
    const int row0 = blockIdx.y * 128;
    const int col0 = blockIdx.x * 128;

    float acc[16][4];
#pragma unroll
    for (int i = 0; i < 16; i++)
#pragma unroll
        for (int j = 0; j < 4; j++) acc[i][j] = 0.f;

    float4 ga[2];
    uint2 gh[2], gl[2];

    auto load_tile = [&](int k0) {
#pragma unroll
        for (int j = 0; j < 2; j++) {
            int idx = j * 256 + tid;
            int m = idx >> 2, kk = (idx & 3) << 2;
            int r = row0 + m;
            ga[j] = make_float4(0.f, 0.f, 0.f, 0.f);
            if (r < Nrows) ga[j] = *(const float4*)&A[(size_t)r * lda + k0 + kk];
            int n = (idx & 63) << 1, bkp = idx >> 6;
            size_t off = (size_t)(k0 / 2 + bkp) * M + col0 + n;
            gh[j] = *(const uint2*)&PBh[off];
            gl[j] = *(const uint2*)&PBl[off];
        }
    };

    load_tile(0);

    for (int k0 = 0; k0 < K; k0 += 16) {
        __syncthreads();
#pragma unroll
        for (int j = 0; j < 2; j++) {
            int idx = j * 256 + tid;
            int m = idx >> 2, kp = (idx & 3) << 1;
            float4 v = ga[j];
            float hx = __bfloat162float(__float2bfloat16(v.x));
            float hy = __bfloat162float(__float2bfloat16(v.y));
            float hz = __bfloat162float(__float2bfloat16(v.z));
            float hw = __bfloat162float(__float2bfloat16(v.w));
            sAh[m][kp]     = pack_bf16(hx, hy);
            sAh[m][kp + 1] = pack_bf16(hz, hw);
            sAl[m][kp]     = pack_bf16(v.x - hx, v.y - hy);
            sAl[m][kp + 1] = pack_bf16(v.z - hz, v.w - hw);

            int n = (idx & 63) << 1, bkp = idx >> 6;
            sBh[n][bkp]     = gh[j].x;
            sBh[n + 1][bkp] = gh[j].y;
            sBl[n][bkp]     = gl[j].x;
            sBl[n + 1][bkp] = gl[j].y;
        }
        __syncthreads();

        if (k0 + 16 < K) load_tile(k0 + 16);

        unsigned af[4][4], bh[4][2], bl[4][2];
        const int ar = lane >> 2, ak = lane & 3;
#pragma unroll
        for (int i = 0; i < 4; i++) {
            int m = wm + i * 16 + ar;
            af[i][0] = sAh[m][ak];
            af[i][1] = sAh[m + 8][ak];
            af[i][2] = sAh[m][ak + 4];
            af[i][3] = sAh[m + 8][ak + 4];
        }
#pragma unroll
        for (int j = 0; j < 4; j++) {
            int nn = wn + j * 8 + (lane >> 2);
            bh[j][0] = sBh[nn][lane & 3];
            bh[j][1] = sBh[nn][(lane & 3) + 4];
            bl[j][0] = sBl[nn][lane & 3];
            bl[j][1] = sBl[nn][(lane & 3) + 4];
        }
#pragma unroll
        for (int i = 0; i < 4; i++)
#pragma unroll
            for (int j = 0; j < 4; j++) mma_bf16(acc[i * 4 + j], af[i], bh[j]);
#pragma unroll
        for (int i = 0; i < 4; i++)
#pragma unroll
            for (int j = 0; j < 4; j++) mma_bf16(acc[i * 4 + j], af[i], bl[j]);
#pragma unroll
        for (int i = 0; i < 4; i++) {
            int m = wm + i * 16 + ar;
            af[i][0] = sAl[m][ak];
            af[i][1] = sAl[m + 8][ak];
            af[i][2] = sAl[m][ak + 4];
            af[i][3] = sAl[m + 8][ak + 4];
        }
#pragma unroll
        for (int i = 0; i < 4; i++)
#pragma unroll
            for (int j = 0; j < 4; j++) mma_bf16(acc[i * 4 + j], af[i], bh[j]);
    }

    // epilogue
#pragma unroll
    for (int i = 0; i < 4; i++) {
#pragma unroll
        for (int j = 0; j < 4; j++) {
            int r = row0 + wm + i * 16 + (lane >> 2);
            int c = col0 + wn + j * 8 + (lane & 3) * 2;
            float* ap = acc[i * 4 + j];
#pragma unroll
            for (int h = 0; h < 2; h++) {
                int rr = r + h * 8;
                if (rr >= Nrows) continue;
                float v0 = ap[h * 2 + 0] + bias[c];
                float v1 = ap[h * 2 + 1] + bias[c + 1];
                if (gamma != nullptr) {
                    v0 = gamma[c] * (v0 * bn_inv) + beta[c];
                    v1 = gamma[c + 1] * (v1 * bn_inv) + beta[c + 1];
                }
                if (ACT == 1) { v0 = leaky1(v0); v1 = leaky1(v1); }
                else if (ACT == 2) { v0 = dleaky(v0); v1 = dleaky(v1); }
                *(float2*)&Cmat[(size_t)rr * ldc + c] = make_float2(v0, v1);
            }
        }
    }
}

// ---------------------------------------------------------------------------
// Pooling
// ---------------------------------------------------------------------------
__global__ void zero_pool_kernel() {
    int idx = blockIdx.x * blockDim.x + threadIdx.x;
    if (idx < NMOL * 128 / 4)
        *(float4*)&g_pool[idx * 4] = make_float4(0.f, 0.f, 0.f, 0.f);
}

__global__ void pool_kernel(const int* __restrict__ batch) {
    int idx = blockIdx.x * blockDim.x + threadIdx.x;
    int n = idx >> 5;
    if (n >= NN) return;
    int c4 = (idx & 31) << 2;
    float4 v = *(const float4*)&g_HS[(size_t)n * HSW + 384 + c4];
    float* p = g_pool + (size_t)batch[n] * 128 + c4;
    asm volatile("red.global.add.v4.f32 [%0], {%1,%2,%3,%4};"
                 :: "l"(p), "f"(v.x), "f"(v.y), "f"(v.z), "f"(v.w) : "memory");
}

__global__ void bcast_kernel(const int* __restrict__ batch) {
    int idx = blockIdx.x * blockDim.x + threadIdx.x;
    int n = idx >> 5;
    if (n >= NN) return;
    int c4 = (idx & 31) << 2;
    float4 v = *(const float4*)&g_pool[(size_t)batch[n] * 128 + c4];
    *(float4*)&g_HS[(size_t)n * HSW + 512 + c4] = v;
}

// ---------------------------------------------------------------------------
// Final: out[n] = sigmoid(Z1[n,:] . fW + fb)
// ---------------------------------------------------------------------------
__global__ void final_kernel(const float* __restrict__ Z,
                             const float* __restrict__ fW,
                             const float* __restrict__ fb,
                             float* __restrict__ out) {
    int idx = blockIdx.x * blockDim.x + threadIdx.x;
    int n = idx >> 5;
    if (n >= NN) return;
    int lane = idx & 31;
    float s = 0.f;
#pragma unroll
    for (int j = lane; j < CLSD; j += 32)
        s = fmaf(Z[(size_t)n * CLSD + j], fW[j], s);
#pragma unroll
    for (int o = 16; o; o >>= 1) s += __shfl_xor_sync(0xffffffffu, s, o);
    if (lane == 0) {
        float z = s + fb[0];
        out[n] = 1.f / (1.f + expf(-z));
    }
}

// ---------------------------------------------------------------------------
// Launch
// ---------------------------------------------------------------------------
extern "C" void kernel_launch(void* const* d_in, const int* in_sizes, int n_in,
                              void* d_out, int out_size) {
    const float* x    = (const float*)d_in[0];
    const int*   ei   = (const int*)d_in[1];
    const float* attr = (const float*)d_in[2];
    const int*   batch= (const int*)d_in[3];
    const float* c1W  = (const float*)d_in[4];
    const float* c1b  = (const float*)d_in[5];
    const float* c1g  = (const float*)d_in[6];
    const float* c1be = (const float*)d_in[7];
    const float* c1eW = (const float*)d_in[8];
    const float* c1eb = (const float*)d_in[9];
    const float* cW   = (const float*)d_in[10];
    const float* cb   = (const float*)d_in[11];
    const float* cg   = (const float*)d_in[12];
    const float* cbe  = (const float*)d_in[13];
    const float* ceW  = (const float*)d_in[14];
    const float* ceb  = (const float*)d_in[15];
    const float* k1W  = (const float*)d_in[16];
    const float* k1b  = (const float*)d_in[17];
    const float* kW   = (const float*)d_in[18];
    const float* kb   = (const float*)d_in[19];
    const float* fW   = (const float*)d_in[20];
    const float* fb   = (const float*)d_in[21];
    float* out = (float*)d_out;

    const int* srcp = ei;
    const int* dstp = ei + EE;

    const float bn_inv = (float)(1.0 / (double)((float)sqrt(1.0 + 1e-5)));

    float *agg, *h0, *HS, *z1, *z2;
    unsigned *Bh, *Bl;
    cudaGetSymbolAddress((void**)&agg, g_agg);
    cudaGetSymbolAddress((void**)&h0,  g_h0);
    cudaGetSymbolAddress((void**)&HS,  g_HS);
    cudaGetSymbolAddress((void**)&z1,  g_z1);
    cudaGetSymbolAddress((void**)&z2,  g_z2);
    cudaGetSymbolAddress((void**)&Bh,  g_Bh);
    cudaGetSymbolAddress((void**)&Bl,  g_Bl);

    // ---- CSR build + weight conversion ----
    wcvt_count_kernel<<<CNT_BLK + WCVT_BLK, 256>>>(dstp, c1W, cW, k1W, kW);
    csr_scan_kernel<<<1, 1024>>>();
    fill_permute_kernel<<<(EE * 4 + 255) / 256, 256>>>(srcp, dstp, attr);

    // ---- conv1 (64 -> 128): 1 warp per node ----
    {
        gather_kernel<1><<<(NN + 3) / 4, 128>>>(x, INRR, c1eW, c1eb, agg);
        dim3 grid(1, (NN + 127) / 128);
        bf16_gemm<2><<<grid, 256>>>(agg, 64, Bh + WC1_OFF, Bl + WC1_OFF,
                                    c1b, c1g, c1be, h0, 128, NN, 64, 128, bn_inv);
    }

    // ---- conv loop (4 layers, 128 -> 128): 2 warps per node, C=2 each ----
    for (int i = 0; i < 4; i++) {
        const float* inPtr = (i == 0) ? h0 : (HS + (size_t)(i - 1) * 128);
        int ldin = (i == 0) ? 128 : HSW;
        gather_kernel<2><<<(NN * 2 + 3) / 4, 128>>>(inPtr, ldin,
                                                   ceW + (size_t)i * EDD * OUTD,
                                                   ceb + (size_t)i * OUTD, agg);
        dim3 grid(1, (NN + 127) / 128);
        bf16_gemm<2><<<grid, 256>>>(agg, 128,
                                    Bh + WCV_OFF + (size_t)i * 8192,
                                    Bl + WCV_OFF + (size_t)i * 8192,
                                    cb + (size_t)i * OUTD,
                                    cg + (size_t)i * OUTD,
                                    cbe + (size_t)i * OUTD,
                                    HS + (size_t)i * 128, HSW,
                                    NN, 128, 128, bn_inv);
    }

    // ---- global_add_pool + broadcast ----
    zero_pool_kernel<<<(NMOL * 128 / 4 + 255) / 256, 256>>>();
    pool_kernel<<<(NN * 32 + 255) / 256, 256>>>(batch);
    bcast_kernel<<<(NN * 32 + 255) / 256, 256>>>(batch);

    // ---- classifier ----
    {
        dim3 grid1(CLSD / 128, (NN + 127) / 128);
        bf16_gemm<0><<<grid1, 256>>>(HS, HSW, Bh + WK1_OFF, Bl + WK1_OFF,
                                     k1b, nullptr, nullptr,
                                     z1, CLSD, NN, HSW, CLSD, bn_inv);
        bf16_gemm<1><<<grid1, 256>>>(z1, CLSD, Bh + WK2_OFF, Bl + WK2_OFF,
                                     kb, nullptr, nullptr,
                                     z2, CLSD, NN, CLSD, CLSD, bn_inv);
        bf16_gemm<1><<<grid1, 256>>>(z2, CLSD, Bh + WK3_OFF, Bl + WK3_OFF,
                                     kb + CLSD, nullptr, nullptr,
                                     z1, CLSD, NN, CLSD, CLSD, bn_inv);
    }

    // ---- final dot + sigmoid ----
    final_kernel<<<(NN * 32 + 255) / 256, 256>>>(z1, fW, fb, out);
}